// round 11
// baseline (speedup 1.0000x reference)
#include <cuda_runtime.h>

#define N_FEAT   64
#define N_GATES  64
#define N_OUT    8
#define BASE_C   66                   // N_FEAT + 2
#define MAX_CONN 130
#define BT       128                  // threads per block = samples per tile
#define COLB     512                  // bytes per buffer column (128 floats)
#define BUF_BYTES (MAX_CONN * COLB)   // 66,560
#define NBLOCKS  444                  // 148 SMs x 3 resident blocks

// setup outputs (device), index table copied into __constant__
__device__ int2               d_idx[N_GATES];
__device__ float              g_w[N_GATES * N_OUT];   // W[i][j]*scale[j]
__device__ unsigned long long g_smask;                // bit i: gate i output read later

__constant__ int2 c_idx[N_GATES];   // {off(c1)|flag1, off(c2)|flag2}

// byte offset of column c in the swizzled buffer (s baked in, see kernel)
__host__ __device__ __forceinline__ int col_off(int c) {
    int s = (c < 64) ? ((2 * (c >> 2)) & 31) : 0;
    return c * COLB + s * 4;
}

// ---------------------------------------------------------------------------
// Setup: top-2 of masked logits per gate (softmax monotone -> top-2 of
// logits; strict > matches jax.lax.top_k; a*b symmetric so only the index
// set matters). Emits swizzle-baked byte offsets with a "late" flag in bit0
// when the operand references gate i-1 or i-2 (i.e. not yet stored when the
// distance-3 prefetch issues). Folds output_scale into W; builds dead-store
// mask.
// ---------------------------------------------------------------------------
__global__ void setup_kernel(const float* __restrict__ gw,
                             const float* __restrict__ W,
                             const float* __restrict__ scale) {
    __shared__ int s1[N_GATES], s2[N_GATES];
    int t = threadIdx.x;
    if (t < N_GATES) {
        int lim = BASE_C + t;
        float v1 = -3.0e38f, v2 = -3.0e38f;
        int i1 = 0, i2 = 0;
        for (int j = 0; j < lim; j++) {
            float v = gw[t * MAX_CONN + j];
            if (v > v1) { v2 = v1; i2 = i1; v1 = v; i1 = j; }
            else if (v > v2) { v2 = v; i2 = j; }
        }
        s1[t] = i1; s2[t] = i2;
        int f1 = (i1 >= BASE_C + t - 2) ? 1 : 0;   // refs gate t-1 / t-2
        int f2 = (i2 >= BASE_C + t - 2) ? 1 : 0;
        d_idx[t] = make_int2(col_off(i1) | f1, col_off(i2) | f2);
    }
    if (t < N_GATES * N_OUT)
        g_w[t] = W[t] * scale[t & 7];
    __syncthreads();
    if (t == 0) {
        unsigned long long m = 0ull;
        for (int i = 0; i < N_GATES; i++) {
            if (s1[i] >= BASE_C) m |= 1ull << (s1[i] - BASE_C);
            if (s2[i] >= BASE_C) m |= 1ull << (s2[i] - BASE_C);
        }
        g_smask = m;
    }
}

__device__ __forceinline__ unsigned long long fma2(unsigned long long a,
                                                   unsigned long long b,
                                                   unsigned long long c) {
    unsigned long long d;
    asm("fma.rn.f32x2 %0, %1, %2, %3;" : "=l"(d) : "l"(a), "l"(b), "l"(c));
    return d;
}
__device__ __forceinline__ unsigned long long dup2(float g) {
    unsigned long long r;
    unsigned int u = __float_as_uint(g);
    asm("mov.b64 %0, {%1,%1};" : "=l"(r) : "r"(u));
    return r;
}
__device__ __forceinline__ float2 unpack2(unsigned long long v) {
    float2 r;
    asm("mov.b64 {%0,%1}, %2;" : "=f"(r.x), "=f"(r.y) : "l"(v));
    return r;
}

// ---------------------------------------------------------------------------
// Persistent main kernel. Buffer: XOR-swizzled column storage,
//   elem(c, r) at byte   c*512 + ((r ^ s(c)) * 4),  s(c)=2*(c>>2)&31 (X cols),
//   s=0 for const/gate columns. All column reads are lane-permutations
// (conflict-free) and the staging transpose stores are PROVEN conflict-free
// (bank = v | (base^u) covers all 32). Thread-side address = table ^ (tid*4),
// one LOP3. Index table in __constant__ (uniform port, off L1). Gate loop:
// distance-3 operand value prefetch, flag-bit patch reloads, dead-store mask,
// f32x2 output-pair accumulation with smem W broadcasts. X for tile t+1 is
// LDG-prefetched into registers during tile t's gate loop.
// ---------------------------------------------------------------------------
__global__ void __launch_bounds__(BT, 3) circuit_kernel(
    const float* __restrict__ X,
    float* __restrict__ out,
    int n)
{
    extern __shared__ float smem[];
    char*  bufc = (char*)smem;                        // BUF_BYTES
    float* sw   = smem + (BUF_BYTES / 4);             // 512 floats W, 16B aligned

    const int tid   = threadIdx.x;
    const int tidx4 = tid * 4;
    const int nt    = (n + BT - 1) / BT;

    // one-time: stage W, constant columns
    #pragma unroll
    for (int k = 0; k < (N_GATES * N_OUT) / BT; k++)
        sw[tid + k * BT] = g_w[tid + k * BT];
    *(float*)(bufc + 64 * COLB + tidx4) = 0.0f;       // const 0 (s=0)
    *(float*)(bufc + 65 * COLB + tidx4) = 1.0f;       // const 1 (s=0)

    const unsigned long long smask = g_smask;
    char* gstore = bufc + BASE_C * COLB + tidx4;      // gate-region base (s=0)

    const float4* xb4 = (const float4*)X;
    const long long lim4 = ((long long)n * N_FEAT) >> 2;
    const int u    = tid & 15;                        // c>>2 of my 4 stage cols
    const int col0 = 4 * u;
    const int su   = (2 * u) & 31;                    // swizzle for my cols
    const int row0 = tid >> 4;

    // prefetch X for my first tile
    float4 xr[16];
    {
        const long long b4 = (long long)blockIdx.x * (BT * N_FEAT / 4);
        #pragma unroll
        for (int kk = 0; kk < 16; kk++) {
            const long long i4 = b4 + tid + BT * kk;
            xr[kk] = (i4 < lim4) ? xb4[i4] : make_float4(0.f, 0.f, 0.f, 0.f);
        }
    }
    __syncthreads();

    for (int tile = blockIdx.x; tile < nt; tile += NBLOCKS) {
        // ---- swizzled transpose of staged registers (conflict-free STS) ----
        #pragma unroll
        for (int kk = 0; kk < 16; kk++) {
            const int rx = ((row0 + 8 * kk) ^ su) * 4;    // byte row offset
            *(float*)(bufc + (col0 + 0) * COLB + rx) = xr[kk].x;
            *(float*)(bufc + (col0 + 1) * COLB + rx) = xr[kk].y;
            *(float*)(bufc + (col0 + 2) * COLB + rx) = xr[kk].z;
            *(float*)(bufc + (col0 + 3) * COLB + rx) = xr[kk].w;
        }
        __syncthreads();

        // ---- issue LDGs for the NEXT tile; land during the gate loop ----
        const int ntile = tile + NBLOCKS;
        if (ntile < nt) {
            const long long b4 = (long long)ntile * (BT * N_FEAT / 4);
            #pragma unroll
            for (int kk = 0; kk < 16; kk++) {
                const long long i4 = b4 + tid + BT * kk;
                xr[kk] = (i4 < lim4) ? xb4[i4] : make_float4(0.f, 0.f, 0.f, 0.f);
            }
        }

        // ---- gate loop ----
        unsigned long long acc0 = 0ull, acc1 = 0ull, acc2 = 0ull, acc3 = 0ull;

        float pa[4], pb[4];
        #pragma unroll
        for (int j = 0; j < 3; j++) {                 // prologue: gates 0..2
            const int2 t2 = c_idx[j];
            pa[j] = *(const float*)(bufc + ((t2.x & ~3) ^ tidx4));
            pb[j] = *(const float*)(bufc + ((t2.y & ~3) ^ tidx4));
        }

        #pragma unroll
        for (int i = 0; i < N_GATES; i++) {
            const int s = i & 3;
            float a = pa[s], b = pb[s];
            const int2 t2 = c_idx[i];                 // uniform-port load

            // flagged operands reference gate i-1/i-2: reload after their STS
            if (t2.x & 1) a = *(const float*)(bufc + ((t2.x & ~3) ^ tidx4));
            if (t2.y & 1) b = *(const float*)(bufc + ((t2.y & ~3) ^ tidx4));

            const float g = 1.0f - a * b;
            if ((smask >> i) & 1)
                *(float*)(gstore + i * COLB) = g;     // contiguous, 1 wf

            const unsigned long long gg = dup2(g);
            const ulonglong2* wr = (const ulonglong2*)(sw + i * N_OUT);
            ulonglong2 w01 = wr[0], w23 = wr[1];      // 2x LDS.128 broadcast
            acc0 = fma2(gg, w01.x, acc0);
            acc1 = fma2(gg, w01.y, acc1);
            acc2 = fma2(gg, w23.x, acc2);
            acc3 = fma2(gg, w23.y, acc3);

            // prefetch operand VALUES for gate i+3 (indices come from cbank)
            if (i + 3 < N_GATES) {
                const int s3 = (i + 3) & 3;
                const int2 t3 = c_idx[i + 3];
                pa[s3] = *(const float*)(bufc + ((t3.x & ~3) ^ tidx4));
                pb[s3] = *(const float*)(bufc + ((t3.y & ~3) ^ tidx4));
            }
        }

        // ---- epilogue (scale prefolded into W) ----
        const long long row = (long long)tile * BT + tid;
        if (row < n) {
            float2 r01 = unpack2(acc0), r23 = unpack2(acc1);
            float2 r45 = unpack2(acc2), r67 = unpack2(acc3);
            float4* ov = (float4*)(out + row * N_OUT);
            ov[0] = make_float4(r01.x, r01.y, r23.x, r23.y);
            ov[1] = make_float4(r45.x, r45.y, r67.x, r67.y);
        }

        __syncthreads();   // buffer reads done before next tile's transpose
    }
}

// ---------------------------------------------------------------------------
extern "C" void kernel_launch(void* const* d_in, const int* in_sizes, int n_in,
                              void* d_out, int out_size) {
    const float* X     = (const float*)d_in[0];
    const float* gw    = (const float*)d_in[1];
    const float* W     = (const float*)d_in[2];
    const float* scale = (const float*)d_in[3];
    float* out = (float*)d_out;

    const int n = in_sizes[0] / N_FEAT;

    setup_kernel<<<1, N_GATES * N_OUT>>>(gw, W, scale);

    // index table -> constant bank (async D2D, graph-capturable; R4-proven)
    void* p_idx = nullptr;
    cudaGetSymbolAddress(&p_idx, d_idx);
    cudaMemcpyToSymbolAsync(c_idx, p_idx, sizeof(int2) * N_GATES, 0,
                            cudaMemcpyDeviceToDevice, 0);

    const size_t smem_bytes = BUF_BYTES +                       // 66,560
                              N_GATES * N_OUT * sizeof(float);  //  2,048 => 68,608

    cudaFuncSetAttribute(circuit_kernel,
                         cudaFuncAttributeMaxDynamicSharedMemorySize,
                         (int)smem_bytes);

    const int nt = (n + BT - 1) / BT;
    const int grid = (nt < NBLOCKS) ? nt : NBLOCKS;
    circuit_kernel<<<grid, BT, smem_bytes>>>(X, out, n);
}